// round 1
// baseline (speedup 1.0000x reference)
#include <cuda_runtime.h>
#include <cuda_bf16.h>
#include <math.h>

// ---------------------------------------------------------------------------
// Problem: N=1024 nodes, F=128, H=256. Complete graph.
//  - GIN aggregation on triu edges == inclusive prefix-sum over rows.
//  - cumsum(X) @ W == cumsum(X @ W)  -> GEMM first, scan after.
//  - leaky(relu(z)) == relu(z).
//  - Edge MLP: hidden = A[src] + B[dst], A = x@ew1[:F]+eb1, B = x@ew1[F:].
// ---------------------------------------------------------------------------

#define NN 1024
#define HH 256

// Scratch (device globals — no allocation allowed)
__device__ float g_buf1[NN * HH];
__device__ float g_buf2[NN * HH];
__device__ float g_A[NN * HH];
__device__ float g_B[NN * HH];

// ---------------------------------------------------------------------------
// Tiled fp32 GEMM: out[M,N] = X[M,K] @ W[K,N] (+bias) (+epilogue)
// TM=TN=64, TK=16, 256 threads, 4x4 per-thread register blocking.
// EPI: 0=none, 1=relu, 2=leaky(0.01)
// ---------------------------------------------------------------------------
#define TM 64
#define TN 64
#define TK 16

template <int EPI>
__global__ void sgemm_k(const float* __restrict__ X, const float* __restrict__ W,
                        const float* __restrict__ bias, float* __restrict__ out,
                        int M, int K, int N) {
    __shared__ float As[TK][68];   // As[k][m], padded (68) to avoid STS conflicts
    __shared__ float Bs[TK][TN];   // Bs[k][n]

    const int t  = threadIdx.x;
    const int tx = t & 15;
    const int ty = t >> 4;
    const int m0 = blockIdx.y * TM;
    const int n0 = blockIdx.x * TN;

    float acc[4][4];
#pragma unroll
    for (int i = 0; i < 4; i++)
#pragma unroll
        for (int j = 0; j < 4; j++) acc[i][j] = 0.f;

    const int la_k = t & 15;   // 0..15
    const int la_m = t >> 4;   // 0..15
    const int lb_n = t & 63;   // 0..63
    const int lb_k = t >> 6;   // 0..3

    for (int k0 = 0; k0 < K; k0 += TK) {
#pragma unroll
        for (int p = 0; p < 4; p++) {
            As[la_k][p * 16 + la_m] = X[(m0 + p * 16 + la_m) * K + k0 + la_k];
        }
#pragma unroll
        for (int p = 0; p < 4; p++) {
            Bs[p * 4 + lb_k][lb_n] = W[(k0 + p * 4 + lb_k) * N + n0 + lb_n];
        }
        __syncthreads();
#pragma unroll
        for (int k = 0; k < TK; k++) {
            float4 a = *(const float4*)&As[k][ty * 4];
            float4 b = *(const float4*)&Bs[k][tx * 4];
            acc[0][0] += a.x * b.x; acc[0][1] += a.x * b.y; acc[0][2] += a.x * b.z; acc[0][3] += a.x * b.w;
            acc[1][0] += a.y * b.x; acc[1][1] += a.y * b.y; acc[1][2] += a.y * b.z; acc[1][3] += a.y * b.w;
            acc[2][0] += a.z * b.x; acc[2][1] += a.z * b.y; acc[2][2] += a.z * b.z; acc[2][3] += a.z * b.w;
            acc[3][0] += a.w * b.x; acc[3][1] += a.w * b.y; acc[3][2] += a.w * b.z; acc[3][3] += a.w * b.w;
        }
        __syncthreads();
    }

#pragma unroll
    for (int i = 0; i < 4; i++) {
        int m = m0 + ty * 4 + i;
#pragma unroll
        for (int j = 0; j < 4; j++) {
            int n = n0 + tx * 4 + j;
            float v = acc[i][j];
            if (bias) v += bias[n];
            if (EPI == 1) v = fmaxf(v, 0.f);
            if (EPI == 2) v = (v >= 0.f) ? v : 0.01f * v;
            out[m * N + n] = v;
        }
    }
}

// ---------------------------------------------------------------------------
// Inclusive column prefix-sum over 1024 rows (C=256 columns), fused epilogue:
//   h = (cumsum + bias) * (g * rsqrt(1+eps)) + bt ; relu
// One block per column, 256 threads, 4 consecutive rows per thread.
// ---------------------------------------------------------------------------
__global__ void cumsum_bn_relu_k(const float* __restrict__ in, float* __restrict__ out,
                                 const float* __restrict__ bias, const float* __restrict__ g,
                                 const float* __restrict__ bt) {
    const int C = HH;
    const int c = blockIdx.x;
    const int t = threadIdx.x;
    __shared__ float ssum[256];

    float v[4];
    float run = 0.f;
    const int base = t * 4;
#pragma unroll
    for (int r = 0; r < 4; r++) {
        v[r] = in[(base + r) * C + c];
        run += v[r];
        v[r] = run;
    }
    ssum[t] = run;
    __syncthreads();
    for (int off = 1; off < 256; off <<= 1) {
        float addv = 0.f;
        if (t >= off) addv = ssum[t - off];
        __syncthreads();
        if (t >= off) ssum[t] += addv;
        __syncthreads();
    }
    float excl = (t > 0) ? ssum[t - 1] : 0.f;
    float sc   = g[c] * rsqrtf(1.f + 1e-5f);
    float bb   = bias[c];
    float btc  = bt[c];
#pragma unroll
    for (int r = 0; r < 4; r++) {
        float h = (v[r] + excl + bb) * sc + btc;
        out[(base + r) * C + c] = fmaxf(h, 0.f);
    }
}

// ---------------------------------------------------------------------------
// Pairwise edge kernel: for i<j, p = sigmoid(sum_h relu(A[i,h]+B[j,h])*w[h] + eb2)
// out[i,j] = out[j,i] = p ; out[i,i] = 0.
// 32x32 pair tile per block; only upper-triangle tiles do work.
// Shared rows padded to 257 floats -> conflict-free LDS in the inner loop.
// ---------------------------------------------------------------------------
#define EPAD 257
#define EDGE_SMEM ((2 * 32 * EPAD + 256) * 4)

__global__ void edge_k(const float* __restrict__ A, const float* __restrict__ Bm,
                       const float* __restrict__ ew2, const float* __restrict__ eb2,
                       float* __restrict__ out) {
    const int ti = blockIdx.y, tj = blockIdx.x;
    if (tj < ti) return;

    extern __shared__ float sh[];
    float* As = sh;                 // 32 * EPAD
    float* Bs = sh + 32 * EPAD;     // 32 * EPAD
    float* ws = sh + 2 * 32 * EPAD; // 256

    const int t = threadIdx.x;
    ws[t] = ew2[t];

    const int i0 = ti * 32, j0 = tj * 32;
#pragma unroll
    for (int p = 0; p < 8; p++) {
        int q = t + 256 * p;         // 0..2047 float4 chunks
        int r = q >> 6;              // row 0..31
        int c = (q & 63) << 2;       // col
        float4 va = *(const float4*)&A[(i0 + r) * HH + c];
        As[r * EPAD + c + 0] = va.x; As[r * EPAD + c + 1] = va.y;
        As[r * EPAD + c + 2] = va.z; As[r * EPAD + c + 3] = va.w;
        float4 vb = *(const float4*)&Bm[(j0 + r) * HH + c];
        Bs[r * EPAD + c + 0] = vb.x; Bs[r * EPAD + c + 1] = vb.y;
        Bs[r * EPAD + c + 2] = vb.z; Bs[r * EPAD + c + 3] = vb.w;
    }
    __syncthreads();

    const int tx = t & 15, ty = t >> 4;
    const int ia = ty * 2, ja = tx * 2;
    const float* a0p = &As[ia * EPAD];
    const float* a1p = &As[(ia + 1) * EPAD];
    const float* b0p = &Bs[ja * EPAD];
    const float* b1p = &Bs[(ja + 1) * EPAD];

    float s00 = 0.f, s01 = 0.f, s10 = 0.f, s11 = 0.f;
#pragma unroll 8
    for (int h = 0; h < HH; h++) {
        float w  = ws[h];
        float a0 = a0p[h], a1 = a1p[h];
        float b0 = b0p[h], b1 = b1p[h];
        s00 = fmaf(fmaxf(a0 + b0, 0.f), w, s00);
        s01 = fmaf(fmaxf(a0 + b1, 0.f), w, s01);
        s10 = fmaf(fmaxf(a1 + b0, 0.f), w, s10);
        s11 = fmaf(fmaxf(a1 + b1, 0.f), w, s11);
    }

    const float e2 = eb2[0];
    float s[2][2] = {{s00, s01}, {s10, s11}};
#pragma unroll
    for (int di = 0; di < 2; di++) {
#pragma unroll
        for (int dj = 0; dj < 2; dj++) {
            int gi = i0 + ia + di;
            int gj = j0 + ja + dj;
            if (gi < gj) {
                float pv = 1.f / (1.f + expf(-(s[di][dj] + e2)));
                out[gi * NN + gj] = pv;
                out[gj * NN + gi] = pv;
            } else if (gi == gj) {
                out[gi * NN + gi] = 0.f;
            }
        }
    }
}

// ---------------------------------------------------------------------------
extern "C" void kernel_launch(void* const* d_in, const int* in_sizes, int n_in,
                              void* d_out, int out_size) {
    (void)in_sizes; (void)n_in; (void)out_size;
    const float* x0  = (const float*)d_in[0];
    const float* w1a = (const float*)d_in[1];
    const float* b1a = (const float*)d_in[2];
    const float* g1  = (const float*)d_in[3];
    const float* bt1 = (const float*)d_in[4];
    const float* w1b = (const float*)d_in[5];
    const float* b1b = (const float*)d_in[6];
    const float* w2a = (const float*)d_in[7];
    const float* b2a = (const float*)d_in[8];
    const float* g2  = (const float*)d_in[9];
    const float* bt2 = (const float*)d_in[10];
    const float* w2b = (const float*)d_in[11];
    const float* b2b = (const float*)d_in[12];
    const float* lw1 = (const float*)d_in[13];
    const float* lb1 = (const float*)d_in[14];
    const float* lw2 = (const float*)d_in[15];
    const float* lb2 = (const float*)d_in[16];
    const float* ew1 = (const float*)d_in[17];
    const float* eb1 = (const float*)d_in[18];
    const float* ew2 = (const float*)d_in[19];
    const float* eb2 = (const float*)d_in[20];
    float* out = (float*)d_out;

    float *B1, *B2, *Ap, *Bp;
    cudaGetSymbolAddress((void**)&B1, g_buf1);
    cudaGetSymbolAddress((void**)&B2, g_buf2);
    cudaGetSymbolAddress((void**)&Ap, g_A);
    cudaGetSymbolAddress((void**)&Bp, g_B);

    const dim3 blk(256);
    const dim3 g_n256(256 / TN, NN / TM);   // (4,16)
    const dim3 g_n128(128 / TN, NN / TM);   // (2,16)

    // GIN layer 1: cumsum(x0 @ w1a) -> BN/relu -> @w1b relu (leaky is no-op)
    sgemm_k<0><<<g_n256, blk>>>(x0, w1a, nullptr, B1, NN, 128, 256);
    cumsum_bn_relu_k<<<256, 256>>>(B1, B2, b1a, g1, bt1);
    sgemm_k<1><<<g_n256, blk>>>(B2, w1b, b1b, B1, NN, 256, 256);

    // GIN layer 2
    sgemm_k<0><<<g_n256, blk>>>(B1, w2a, nullptr, B2, NN, 256, 256);
    cumsum_bn_relu_k<<<256, 256>>>(B2, B1, b2a, g2, bt2);
    sgemm_k<1><<<g_n128, blk>>>(B1, w2b, b2b, B2, NN, 256, 128);

    // Linear head
    sgemm_k<2><<<g_n256, blk>>>(B2, lw1, lb1, B1, NN, 128, 256);
    sgemm_k<0><<<g_n128, blk>>>(B1, lw2, lb2, B2, NN, 256, 128);

    // Edge feature halves: A = x3 @ ew1[:128] + eb1 ; B = x3 @ ew1[128:]
    sgemm_k<0><<<g_n256, blk>>>(B2, ew1, eb1, Ap, NN, 128, 256);
    sgemm_k<0><<<g_n256, blk>>>(B2, ew1 + 128 * HH, nullptr, Bp, NN, 128, 256);

    // Pairwise edge probabilities
    cudaFuncSetAttribute(edge_k, cudaFuncAttributeMaxDynamicSharedMemorySize, EDGE_SMEM);
    edge_k<<<dim3(32, 32), blk, EDGE_SMEM>>>(Ap, Bp, ew2, eb2, out);
}

// round 3
// speedup vs baseline: 1.2956x; 1.2956x over previous
#include <cuda_runtime.h>
#include <cuda_bf16.h>
#include <math.h>

// ---------------------------------------------------------------------------
// N=1024 nodes, F=128, H=256, complete graph.
//  - GIN aggregation on triu edges == inclusive prefix-sum over rows.
//  - cumsum(X) @ W == cumsum(X @ W)  -> GEMM first, scan after.
//  - leaky(relu(z)) == relu(z).
//  - Edge MLP: hidden = A[src] + B[dst], A = x@ew1[:F]+eb1, B = x@ew1[F:].
// ---------------------------------------------------------------------------

#define NN 1024
#define HH 256

__device__ float g_buf1[NN * HH];
__device__ float g_buf2[NN * HH];
__device__ float g_A[NN * HH];
__device__ float g_B[NN * HH];

// ---------------------------------------------------------------------------
// GEMM v2: out[M,N] = X[M,K] @ W[K,N] (+bias)(+epilogue)
// TM=32 rows, TN in {64,32}, TK=32, 256 threads, micro-tile 2 x (TN/16).
// Grid is (N/TN, 32[, 2]) = 128 (or 256) blocks -> fills the chip.
// DUAL: blockIdx.z==1 computes X @ W2 -> out2 (no bias) in the same launch.
// EPI: 0=none, 1=relu, 2=leaky(0.01)
// ---------------------------------------------------------------------------
template <int K, int N, int TN, int EPI, int DUAL>
__global__ __launch_bounds__(256) void sgemm2(
    const float* __restrict__ X, const float* __restrict__ W,
    const float* __restrict__ W2, const float* __restrict__ bias,
    float* __restrict__ out, float* __restrict__ out2) {

    constexpr int TK = 32;
    constexpr int MN = TN / 16;      // 4 or 2 cols per thread
    __shared__ float As[TK][34];     // [k][m], pad 34 keeps float2 aligned
    __shared__ float Bs[TK][TN];

    const int t  = threadIdx.x;
    const int tx = t & 15;
    const int ty = t >> 4;
    const int m0 = blockIdx.y * 32;
    const int n0 = blockIdx.x * TN;

    const float* Wp = W;
    const float* bp = bias;
    float*       op = out;
    if (DUAL && blockIdx.z) { Wp = W2; bp = nullptr; op = out2; }

    float acc[2][MN];
#pragma unroll
    for (int i = 0; i < 2; i++)
#pragma unroll
        for (int j = 0; j < MN; j++) acc[i][j] = 0.f;

    const int xr = t >> 3;            // 0..31 row within X tile
    const int xc = (t & 7) * 4;       // k offset (float4)
    constexpr int NCH = (TK * TN) / (256 * 4);  // W float4 chunks per thread

    for (int k0 = 0; k0 < K; k0 += TK) {
        // X tile -> As (transposed)
        float4 xv = *(const float4*)&X[(m0 + xr) * K + k0 + xc];
        As[xc + 0][xr] = xv.x; As[xc + 1][xr] = xv.y;
        As[xc + 2][xr] = xv.z; As[xc + 3][xr] = xv.w;
        // W tile -> Bs
#pragma unroll
        for (int p = 0; p < NCH; p++) {
            int idx = t + 256 * p;
            int wr  = (idx * 4) / TN;
            int wc  = (idx * 4) % TN;
            *(float4*)&Bs[wr][wc] = *(const float4*)&Wp[(k0 + wr) * N + n0 + wc];
        }
        __syncthreads();
#pragma unroll
        for (int k = 0; k < TK; k++) {
            float2 a = *(const float2*)&As[k][ty * 2];
            if (MN == 4) {
                float4 b = *(const float4*)&Bs[k][tx * 4];
                acc[0][0] = fmaf(a.x, b.x, acc[0][0]);
                acc[0][1] = fmaf(a.x, b.y, acc[0][1]);
                acc[0][2] = fmaf(a.x, b.z, acc[0][2]);
                acc[0][3] = fmaf(a.x, b.w, acc[0][3]);
                acc[1][0] = fmaf(a.y, b.x, acc[1][0]);
                acc[1][1] = fmaf(a.y, b.y, acc[1][1]);
                acc[1][2] = fmaf(a.y, b.z, acc[1][2]);
                acc[1][3] = fmaf(a.y, b.w, acc[1][3]);
            } else {
                float2 b = *(const float2*)&Bs[k][tx * 2];
                acc[0][0] = fmaf(a.x, b.x, acc[0][0]);
                acc[0][1] = fmaf(a.x, b.y, acc[0][1]);
                acc[1][0] = fmaf(a.y, b.x, acc[1][0]);
                acc[1][1] = fmaf(a.y, b.y, acc[1][1]);
            }
        }
        __syncthreads();
    }

#pragma unroll
    for (int i = 0; i < 2; i++) {
        int m = m0 + ty * 2 + i;
#pragma unroll
        for (int j = 0; j < MN; j++) {
            int n = n0 + tx * MN + j;
            float v = acc[i][j];
            if (bp) v += bp[n];
            if (EPI == 1) v = fmaxf(v, 0.f);
            if (EPI == 2) v = (v >= 0.f) ? v : 0.01f * v;
            op[m * N + n] = v;
        }
    }
}

// ---------------------------------------------------------------------------
// Inclusive column prefix-sum over 1024 rows (256 cols), fused BN+relu:
//   h = (cumsum + bias) * (g * rsqrt(1+eps)) + bt ; relu
// ---------------------------------------------------------------------------
__global__ void cumsum_bn_relu_k(const float* __restrict__ in, float* __restrict__ out,
                                 const float* __restrict__ bias, const float* __restrict__ g,
                                 const float* __restrict__ bt) {
    const int C = HH;
    const int c = blockIdx.x;
    const int t = threadIdx.x;
    __shared__ float ssum[256];

    float v[4];
    float run = 0.f;
    const int base = t * 4;
#pragma unroll
    for (int r = 0; r < 4; r++) {
        v[r] = in[(base + r) * C + c];
        run += v[r];
        v[r] = run;
    }
    ssum[t] = run;
    __syncthreads();
    for (int off = 1; off < 256; off <<= 1) {
        float addv = 0.f;
        if (t >= off) addv = ssum[t - off];
        __syncthreads();
        if (t >= off) ssum[t] += addv;
        __syncthreads();
    }
    float excl = (t > 0) ? ssum[t - 1] : 0.f;
    float sc   = g[c] * rsqrtf(1.f + 1e-5f);
    float bb   = bias[c];
    float btc  = bt[c];
#pragma unroll
    for (int r = 0; r < 4; r++) {
        float h = (v[r] + excl + bb) * sc + btc;
        out[(base + r) * C + c] = fmaxf(h, 0.f);
    }
}

// ---------------------------------------------------------------------------
// Edge kernel v2: 64x64 pair tile, 256 threads, 4x4 micro, float4 over h.
// p(i,j) = sigmoid(sum_h relu(A[i,h]+B[j,h]) * w[h] + eb2), write both halves.
// 136 working blocks (triangular) == one full wave on 148 SMs.
// ---------------------------------------------------------------------------
#define ES 260                             // floats per smem row (16B aligned)
#define EDGE_SMEM ((2 * 64 * ES + 256) * 4)

__global__ __launch_bounds__(256) void edge_k(
    const float* __restrict__ A, const float* __restrict__ Bm,
    const float* __restrict__ ew2, const float* __restrict__ eb2,
    float* __restrict__ out) {
    const int ti = blockIdx.y, tj = blockIdx.x;
    if (tj < ti) return;

    extern __shared__ float sh[];
    float* As = sh;                  // 64 * ES
    float* Bs = sh + 64 * ES;        // 64 * ES
    float* ws = sh + 2 * 64 * ES;    // 256

    const int t = threadIdx.x;
    ws[t] = ew2[t];

    const int i0 = ti * 64, j0 = tj * 64;
#pragma unroll
    for (int p = 0; p < 16; p++) {
        int q = t + 256 * p;             // 0..4095 float4 chunks
        int r = q >> 6;                  // row 0..63
        int c = (q & 63) << 2;           // col (float4)
        *(float4*)&As[r * ES + c] = *(const float4*)&A[(i0 + r) * HH + c];
        *(float4*)&Bs[r * ES + c] = *(const float4*)&Bm[(j0 + r) * HH + c];
    }
    __syncthreads();

    const int tx = t & 15, ty = t >> 4;
    const int ia = ty * 4, ja = tx * 4;

    float acc[4][4];
#pragma unroll
    for (int di = 0; di < 4; di++)
#pragma unroll
        for (int dj = 0; dj < 4; dj++) acc[di][dj] = 0.f;

    for (int h = 0; h < HH; h += 4) {
        float4 w4 = *(const float4*)&ws[h];
        float4 av[4], bv[4];
#pragma unroll
        for (int d = 0; d < 4; d++) {
            av[d] = *(const float4*)&As[(ia + d) * ES + h];
            bv[d] = *(const float4*)&Bs[(ja + d) * ES + h];
        }
#pragma unroll
        for (int di = 0; di < 4; di++) {
#pragma unroll
            for (int dj = 0; dj < 4; dj++) {
                float s = acc[di][dj];
                s = fmaf(fmaxf(av[di].x + bv[dj].x, 0.f), w4.x, s);
                s = fmaf(fmaxf(av[di].y + bv[dj].y, 0.f), w4.y, s);
                s = fmaf(fmaxf(av[di].z + bv[dj].z, 0.f), w4.z, s);
                s = fmaf(fmaxf(av[di].w + bv[dj].w, 0.f), w4.w, s);
                acc[di][dj] = s;
            }
        }
    }

    const float e2 = eb2[0];
#pragma unroll
    for (int di = 0; di < 4; di++) {
#pragma unroll
        for (int dj = 0; dj < 4; dj++) {
            int gi = i0 + ia + di;
            int gj = j0 + ja + dj;
            if (gi < gj) {
                float pv = 1.f / (1.f + __expf(-(acc[di][dj] + e2)));
                out[gi * NN + gj] = pv;
                out[gj * NN + gi] = pv;
            } else if (gi == gj) {
                out[gi * NN + gi] = 0.f;
            }
        }
    }
}

// ---------------------------------------------------------------------------
extern "C" void kernel_launch(void* const* d_in, const int* in_sizes, int n_in,
                              void* d_out, int out_size) {
    (void)in_sizes; (void)n_in; (void)out_size;
    const float* x0  = (const float*)d_in[0];
    const float* w1a = (const float*)d_in[1];
    const float* b1a = (const float*)d_in[2];
    const float* g1  = (const float*)d_in[3];
    const float* bt1 = (const float*)d_in[4];
    const float* w1b = (const float*)d_in[5];
    const float* b1b = (const float*)d_in[6];
    const float* w2a = (const float*)d_in[7];
    const float* b2a = (const float*)d_in[8];
    const float* g2  = (const float*)d_in[9];
    const float* bt2 = (const float*)d_in[10];
    const float* w2b = (const float*)d_in[11];
    const float* b2b = (const float*)d_in[12];
    const float* lw1 = (const float*)d_in[13];
    const float* lb1 = (const float*)d_in[14];
    const float* lw2 = (const float*)d_in[15];
    const float* lb2 = (const float*)d_in[16];
    const float* ew1 = (const float*)d_in[17];
    const float* eb1 = (const float*)d_in[18];
    const float* ew2 = (const float*)d_in[19];
    const float* eb2 = (const float*)d_in[20];
    float* out = (float*)d_out;

    float *B1, *B2, *Ap, *Bp;
    cudaGetSymbolAddress((void**)&B1, g_buf1);
    cudaGetSymbolAddress((void**)&B2, g_buf2);
    cudaGetSymbolAddress((void**)&Ap, g_A);
    cudaGetSymbolAddress((void**)&Bp, g_B);

    const dim3 blk(256);
    const dim3 gA(4, 32);        // N=256, TN=64 -> 128 blocks
    const dim3 gB(4, 32);        // N=128, TN=32 -> 128 blocks
    const dim3 gD(4, 32, 2);     // dual edge GEMM -> 256 blocks

    // GIN layer 1
    sgemm2<128, 256, 64, 0, 0><<<gA, blk>>>(x0, w1a, nullptr, nullptr, B1, nullptr);
    cumsum_bn_relu_k<<<256, 256>>>(B1, B2, b1a, g1, bt1);
    sgemm2<256, 256, 64, 1, 0><<<gA, blk>>>(B2, w1b, nullptr, b1b, B1, nullptr);

    // GIN layer 2
    sgemm2<256, 256, 64, 0, 0><<<gA, blk>>>(B1, w2a, nullptr, nullptr, B2, nullptr);
    cumsum_bn_relu_k<<<256, 256>>>(B2, B1, b2a, g2, bt2);
    sgemm2<256, 128, 32, 1, 0><<<gB, blk>>>(B1, w2b, nullptr, b2b, B2, nullptr);

    // Linear head
    sgemm2<128, 256, 64, 2, 0><<<gA, blk>>>(B2, lw1, nullptr, lb1, B1, nullptr);
    sgemm2<256, 128, 32, 0, 0><<<gB, blk>>>(B1, lw2, nullptr, lb2, B2, nullptr);

    // Edge halves in one launch: A = x@ew1[:128]+eb1 ; B = x@ew1[128:]
    sgemm2<128, 256, 64, 0, 1><<<gD, blk>>>(B2, ew1, ew1 + 128 * HH, eb1, Ap, Bp);

    // Pairwise edge probabilities
    (void)cudaFuncSetAttribute(edge_k, cudaFuncAttributeMaxDynamicSharedMemorySize, EDGE_SMEM);
    edge_k<<<dim3(16, 16), blk, EDGE_SMEM>>>(Ap, Bp, ew2, eb2, out);
}

// round 4
// speedup vs baseline: 1.6084x; 1.2414x over previous
#include <cuda_runtime.h>
#include <cuda_bf16.h>
#include <math.h>

// ---------------------------------------------------------------------------
// N=1024 nodes, F=128, H=256, complete graph.
//  - GIN aggregation on triu edges == inclusive prefix-sum over rows.
//  - cumsum(X) @ W == cumsum(X @ W)  -> GEMM first, scan after.
//  - leaky(relu(z)) == relu(z).
//  - Edge MLP: hidden = A[src] + B[dst], A = x@ew1[:F]+eb1, B = x@ew1[F:].
// ---------------------------------------------------------------------------

#define NN 1024
#define HH 256

__device__ float g_buf1[NN * HH];
__device__ float g_buf2[NN * HH];
__device__ float g_A[NN * HH];
__device__ float g_B[NN * HH];

typedef unsigned long long u64;

// ---- packed f32x2 helpers (sm_100a) ---------------------------------------
__device__ __forceinline__ u64 add2(u64 a, u64 b) {
    u64 r; asm("add.rn.f32x2 %0, %1, %2;" : "=l"(r) : "l"(a), "l"(b)); return r;
}
__device__ __forceinline__ u64 fma2(u64 a, u64 b, u64 c) {
    u64 r; asm("fma.rn.f32x2 %0, %1, %2, %3;" : "=l"(r) : "l"(a), "l"(b), "l"(c)); return r;
}
__device__ __forceinline__ u64 relu2(u64 t) {
    unsigned lo, hi;
    asm("mov.b64 {%0, %1}, %2;" : "=r"(lo), "=r"(hi) : "l"(t));
    float flo = fmaxf(__uint_as_float(lo), 0.f);
    float fhi = fmaxf(__uint_as_float(hi), 0.f);
    u64 r;
    asm("mov.b64 %0, {%1, %2};" : "=l"(r)
        : "r"(__float_as_uint(flo)), "r"(__float_as_uint(fhi)));
    return r;
}
__device__ __forceinline__ float sum2(u64 t) {
    unsigned lo, hi;
    asm("mov.b64 {%0, %1}, %2;" : "=r"(lo), "=r"(hi) : "l"(t));
    return __uint_as_float(lo) + __uint_as_float(hi);
}

// ---------------------------------------------------------------------------
// GEMM v4: out[M,N] = X[M,K] @ W[K,N] (+bias)(+epilogue)
// TM=32, TN in {64,32}, TK=32, 256 threads, micro 2 x (TN/16).
// Double-buffered smem + register prefetch, ONE sync per K-iteration.
// DUAL: blockIdx.z==1 computes X @ W2 -> out2 (no bias) in the same launch.
// EPI: 0=none, 1=relu, 2=leaky(0.01)
// ---------------------------------------------------------------------------
template <int K, int N, int TN, int EPI, int DUAL>
__global__ __launch_bounds__(256) void sgemm4(
    const float* __restrict__ X, const float* __restrict__ W,
    const float* __restrict__ W2, const float* __restrict__ bias,
    float* __restrict__ out, float* __restrict__ out2) {

    constexpr int TK  = 32;
    constexpr int MN  = TN / 16;                 // 4 or 2 cols per thread
    constexpr int NIT = K / TK;
    constexpr int WCH = (TK * TN) / (256 * 4);   // W float4 chunks per thread

    __shared__ float As[2][TK][34];              // [buf][k][m]
    __shared__ float Bs[2][TK][TN];              // [buf][k][n]

    const int t  = threadIdx.x;
    const int tx = t & 15;
    const int ty = t >> 4;
    const int m0 = blockIdx.y * 32;
    const int n0 = blockIdx.x * TN;

    const float* Wp = W;
    const float* bp = bias;
    float*       op = out;
    if (DUAL && blockIdx.z) { Wp = W2; bp = nullptr; op = out2; }

    const int xr = t >> 3;                       // 0..31 row in X tile
    const int xc = (t & 7) * 4;                  // k offset (float4)

    int wr[WCH], wc[WCH];
#pragma unroll
    for (int p = 0; p < WCH; p++) {
        int idx = t + 256 * p;
        wr[p] = (idx * 4) / TN;
        wc[p] = (idx * 4) % TN;
    }

    // prefetch tile 0
    float4 xv = *(const float4*)&X[(m0 + xr) * K + xc];
    float4 wv[WCH];
#pragma unroll
    for (int p = 0; p < WCH; p++)
        wv[p] = *(const float4*)&Wp[wr[p] * N + n0 + wc[p]];

    // store tile 0 into buffer 0
    As[0][xc + 0][xr] = xv.x; As[0][xc + 1][xr] = xv.y;
    As[0][xc + 2][xr] = xv.z; As[0][xc + 3][xr] = xv.w;
#pragma unroll
    for (int p = 0; p < WCH; p++)
        *(float4*)&Bs[0][wr[p]][wc[p]] = wv[p];
    __syncthreads();

    float acc[2][MN];
#pragma unroll
    for (int i = 0; i < 2; i++)
#pragma unroll
        for (int j = 0; j < MN; j++) acc[i][j] = 0.f;

#pragma unroll 1
    for (int it = 0; it < NIT; it++) {
        const int cur = it & 1;
        // issue global prefetch for next tile (latency hidden by compute)
        if (it + 1 < NIT) {
            const int k1 = (it + 1) * TK;
            xv = *(const float4*)&X[(m0 + xr) * K + k1 + xc];
#pragma unroll
            for (int p = 0; p < WCH; p++)
                wv[p] = *(const float4*)&Wp[(k1 + wr[p]) * N + n0 + wc[p]];
        }
        // compute on current buffer
#pragma unroll
        for (int k = 0; k < TK; k++) {
            float2 a = *(const float2*)&As[cur][k][ty * 2];
            if (MN == 4) {
                float4 b = *(const float4*)&Bs[cur][k][tx * 4];
                acc[0][0] = fmaf(a.x, b.x, acc[0][0]);
                acc[0][1] = fmaf(a.x, b.y, acc[0][1]);
                acc[0][2] = fmaf(a.x, b.z, acc[0][2]);
                acc[0][3] = fmaf(a.x, b.w, acc[0][3]);
                acc[1][0] = fmaf(a.y, b.x, acc[1][0]);
                acc[1][1] = fmaf(a.y, b.y, acc[1][1]);
                acc[1][2] = fmaf(a.y, b.z, acc[1][2]);
                acc[1][3] = fmaf(a.y, b.w, acc[1][3]);
            } else {
                float2 b = *(const float2*)&Bs[cur][k][tx * 2];
                acc[0][0] = fmaf(a.x, b.x, acc[0][0]);
                acc[0][1] = fmaf(a.x, b.y, acc[0][1]);
                acc[1][0] = fmaf(a.y, b.x, acc[1][0]);
                acc[1][1] = fmaf(a.y, b.y, acc[1][1]);
            }
        }
        // stage next tile into the other buffer
        if (it + 1 < NIT) {
            const int nxt = cur ^ 1;
            As[nxt][xc + 0][xr] = xv.x; As[nxt][xc + 1][xr] = xv.y;
            As[nxt][xc + 2][xr] = xv.z; As[nxt][xc + 3][xr] = xv.w;
#pragma unroll
            for (int p = 0; p < WCH; p++)
                *(float4*)&Bs[nxt][wr[p]][wc[p]] = wv[p];
            __syncthreads();
        }
    }

#pragma unroll
    for (int i = 0; i < 2; i++) {
        int m = m0 + ty * 2 + i;
#pragma unroll
        for (int j = 0; j < MN; j++) {
            int n = n0 + tx * MN + j;
            float v = acc[i][j];
            if (bp) v += bp[n];
            if (EPI == 1) v = fmaxf(v, 0.f);
            if (EPI == 2) v = (v >= 0.f) ? v : 0.01f * v;
            op[m * N + n] = v;
        }
    }
}

// ---------------------------------------------------------------------------
// Inclusive column prefix-sum over 1024 rows (256 cols), fused BN+relu:
//   h = (cumsum + bias) * (g * rsqrt(1+eps)) + bt ; relu
// ---------------------------------------------------------------------------
__global__ void cumsum_bn_relu_k(const float* __restrict__ in, float* __restrict__ out,
                                 const float* __restrict__ bias, const float* __restrict__ g,
                                 const float* __restrict__ bt) {
    const int C = HH;
    const int c = blockIdx.x;
    const int t = threadIdx.x;
    __shared__ float ssum[256];

    float v[4];
    float run = 0.f;
    const int base = t * 4;
#pragma unroll
    for (int r = 0; r < 4; r++) {
        v[r] = in[(base + r) * C + c];
        run += v[r];
        v[r] = run;
    }
    ssum[t] = run;
    __syncthreads();
    for (int off = 1; off < 256; off <<= 1) {
        float addv = 0.f;
        if (t >= off) addv = ssum[t - off];
        __syncthreads();
        if (t >= off) ssum[t] += addv;
        __syncthreads();
    }
    float excl = (t > 0) ? ssum[t - 1] : 0.f;
    float sc   = g[c] * rsqrtf(1.f + 1e-5f);
    float bb   = bias[c];
    float btc  = bt[c];
#pragma unroll
    for (int r = 0; r < 4; r++) {
        float h = (v[r] + excl + bb) * sc + btc;
        out[(base + r) * C + c] = fmaxf(h, 0.f);
    }
}

// ---------------------------------------------------------------------------
// Edge kernel v3: 64x64 pair tile, 256 threads, 4x4 micro with STRIDE-16
// column/row mapping (conflict-free LDS), packed f32x2 math:
//   acc2 += f32x2( relu(a+b) ) * w2   (two h-lanes per instruction)
// p(i,j) = sigmoid(sum_h relu(A[i,h]+B[j,h]) * w[h] + eb2); both halves + diag.
// ---------------------------------------------------------------------------
#define ESA 256
#define ESB 260
#define EDGE_SMEM ((64 * ESA + 64 * ESB + 256) * 4)

__global__ __launch_bounds__(256) void edge_k(
    const float* __restrict__ A, const float* __restrict__ Bm,
    const float* __restrict__ ew2, const float* __restrict__ eb2,
    float* __restrict__ out) {
    const int ti = blockIdx.y, tj = blockIdx.x;
    if (tj < ti) return;

    extern __shared__ float sh[];
    float* As = sh;                       // 64 * 256 (rows broadcast -> no pad)
    float* Bs = sh + 64 * ESA;            // 64 * 260 (pad: stride-1 rows/lane)
    float* ws = sh + 64 * ESA + 64 * ESB; // 256

    const int t = threadIdx.x;
    ws[t] = ew2[t];

    const int i0 = ti * 64, j0 = tj * 64;
#pragma unroll
    for (int p = 0; p < 16; p++) {
        int q = t + 256 * p;              // 0..4095 float4 chunks
        int r = q >> 6;                   // row 0..63
        int c = (q & 63) << 2;            // col
        *(float4*)&As[r * ESA + c] = *(const float4*)&A[(i0 + r) * HH + c];
        *(float4*)&Bs[r * ESB + c] = *(const float4*)&Bm[(j0 + r) * HH + c];
    }
    __syncthreads();

    const int tx = t & 15, ty = t >> 4;

    u64 acc[4][4];
#pragma unroll
    for (int di = 0; di < 4; di++)
#pragma unroll
        for (int dj = 0; dj < 4; dj++) acc[di][dj] = 0ull;

#pragma unroll 2
    for (int h = 0; h < HH; h += 4) {
        u64 w01 = *(const u64*)&ws[h];
        u64 w23 = *(const u64*)&ws[h + 2];
        u64 a01[4], a23[4], b01[4], b23[4];
#pragma unroll
        for (int d = 0; d < 4; d++) {
            ulonglong2 av = *(const ulonglong2*)&As[(ty + 16 * d) * ESA + h];
            a01[d] = av.x; a23[d] = av.y;
            ulonglong2 bv = *(const ulonglong2*)&Bs[(tx + 16 * d) * ESB + h];
            b01[d] = bv.x; b23[d] = bv.y;
        }
#pragma unroll
        for (int di = 0; di < 4; di++) {
#pragma unroll
            for (int dj = 0; dj < 4; dj++) {
                acc[di][dj] = fma2(relu2(add2(a01[di], b01[dj])), w01, acc[di][dj]);
                acc[di][dj] = fma2(relu2(add2(a23[di], b23[dj])), w23, acc[di][dj]);
            }
        }
    }

    const float e2 = eb2[0];
#pragma unroll
    for (int di = 0; di < 4; di++) {
#pragma unroll
        for (int dj = 0; dj < 4; dj++) {
            int gi = i0 + ty + 16 * di;
            int gj = j0 + tx + 16 * dj;
            float s = sum2(acc[di][dj]) + e2;
            if (gi < gj) {
                float pv = 1.f / (1.f + __expf(-s));
                out[gi * NN + gj] = pv;
                out[gj * NN + gi] = pv;
            } else if (gi == gj) {
                out[gi * NN + gi] = 0.f;
            }
        }
    }
}

// ---------------------------------------------------------------------------
extern "C" void kernel_launch(void* const* d_in, const int* in_sizes, int n_in,
                              void* d_out, int out_size) {
    (void)in_sizes; (void)n_in; (void)out_size;
    const float* x0  = (const float*)d_in[0];
    const float* w1a = (const float*)d_in[1];
    const float* b1a = (const float*)d_in[2];
    const float* g1  = (const float*)d_in[3];
    const float* bt1 = (const float*)d_in[4];
    const float* w1b = (const float*)d_in[5];
    const float* b1b = (const float*)d_in[6];
    const float* w2a = (const float*)d_in[7];
    const float* b2a = (const float*)d_in[8];
    const float* g2  = (const float*)d_in[9];
    const float* bt2 = (const float*)d_in[10];
    const float* w2b = (const float*)d_in[11];
    const float* b2b = (const float*)d_in[12];
    const float* lw1 = (const float*)d_in[13];
    const float* lb1 = (const float*)d_in[14];
    const float* lw2 = (const float*)d_in[15];
    const float* lb2 = (const float*)d_in[16];
    const float* ew1 = (const float*)d_in[17];
    const float* eb1 = (const float*)d_in[18];
    const float* ew2 = (const float*)d_in[19];
    const float* eb2 = (const float*)d_in[20];
    float* out = (float*)d_out;

    float *B1, *B2, *Ap, *Bp;
    cudaGetSymbolAddress((void**)&B1, g_buf1);
    cudaGetSymbolAddress((void**)&B2, g_buf2);
    cudaGetSymbolAddress((void**)&Ap, g_A);
    cudaGetSymbolAddress((void**)&Bp, g_B);

    const dim3 blk(256);
    const dim3 gA(4, 32);        // N=256, TN=64 -> 128 blocks
    const dim3 gB(4, 32);        // N=128, TN=32 -> 128 blocks
    const dim3 gD(4, 32, 2);     // dual edge GEMM -> 256 blocks

    // GIN layer 1
    sgemm4<128, 256, 64, 0, 0><<<gA, blk>>>(x0, w1a, nullptr, nullptr, B1, nullptr);
    cumsum_bn_relu_k<<<256, 256>>>(B1, B2, b1a, g1, bt1);
    sgemm4<256, 256, 64, 1, 0><<<gA, blk>>>(B2, w1b, nullptr, b1b, B1, nullptr);

    // GIN layer 2
    sgemm4<256, 256, 64, 0, 0><<<gA, blk>>>(B1, w2a, nullptr, nullptr, B2, nullptr);
    cumsum_bn_relu_k<<<256, 256>>>(B2, B1, b2a, g2, bt2);
    sgemm4<256, 128, 32, 1, 0><<<gB, blk>>>(B1, w2b, nullptr, b2b, B2, nullptr);

    // Linear head
    sgemm4<128, 256, 64, 2, 0><<<gA, blk>>>(B2, lw1, nullptr, lb1, B1, nullptr);
    sgemm4<256, 128, 32, 0, 0><<<gB, blk>>>(B1, lw2, nullptr, lb2, B2, nullptr);

    // Edge halves in one launch: A = x@ew1[:128]+eb1 ; B = x@ew1[128:]
    sgemm4<128, 256, 64, 0, 1><<<gD, blk>>>(B2, ew1, ew1 + 128 * HH, eb1, Ap, Bp);

    // Pairwise edge probabilities
    (void)cudaFuncSetAttribute(edge_k, cudaFuncAttributeMaxDynamicSharedMemorySize, EDGE_SMEM);
    edge_k<<<dim3(16, 16), blk, EDGE_SMEM>>>(Ap, Bp, ew2, eb2, out);
}